// round 12
// baseline (speedup 1.0000x reference)
#include <cuda_runtime.h>
#include <cuda_bf16.h>

#define SEQ   8192
#define DIN   256
#define H     2048
#define H4    8192
#define DOUT  64
#define NCTA  148
#define NTHR  448   // 14 warps
#define OUT_BASE (SEQ * DOUT)   // 524288

// ---------------- device scratch (allowed: __device__ globals) --------------
__device__ __nv_bfloat16 g_Whh[(size_t)H4 * H]; // 33.5 MB bf16 W_hh
__device__ float   g_xg [(size_t)SEQ * H4];     // 256 MB  x @ W_ih^T + b
__device__ float   g_hs [(size_t)SEQ * H];      // 64 MB   h history
__device__ float   g_hbuf[2][H];                // double-buffered h
__device__ float   g_WfcT[H * DOUT];            // W_fc transposed [k][d]
__device__ unsigned g_bar;                      // cumulative grid barrier

// ---------------- prep: bf16 convert, transpose, init ----------------------
__global__ void prep_kernel(const float* __restrict__ Whh,
                            const float* __restrict__ hprev,
                            const float* __restrict__ Wfc)
{
    size_t stride = (size_t)gridDim.x * blockDim.x;
    size_t i0 = (size_t)blockIdx.x * blockDim.x + threadIdx.x;
    const size_t npair = (size_t)H4 * H / 2;
    for (size_t p = i0; p < npair; p += stride) {
        float2 v = ((const float2*)Whh)[p];
        ((__nv_bfloat162*)g_Whh)[p] = __floats2bfloat162_rn(v.x, v.y);
    }
    for (size_t i = i0; i < H; i += stride)
        g_hbuf[0][i] = hprev[i];
    for (size_t i = i0; i < (size_t)H * DOUT; i += stride) {
        int d = (int)(i & (DOUT - 1));
        int k = (int)(i >> 6);
        g_WfcT[i] = Wfc[(size_t)d * H + k];
    }
    if (i0 == 0) g_bar = 0u;
}

// ---------------- xg GEMM: xg[t][r] = sum_k x[t][k] W_ih[r][k] + b ----------
__global__ void xg_kernel(const float* __restrict__ x,
                          const float* __restrict__ Wih,
                          const float* __restrict__ bih,
                          const float* __restrict__ bhh)
{
    __shared__ float As[64][68];
    __shared__ float Bs[64][68];
    const int tid = threadIdx.x;
    const int tx = tid & 15, ty = tid >> 4;
    const int t0 = blockIdx.y * 64, r0 = blockIdx.x * 64;

    float acc[4][4];
#pragma unroll
    for (int a = 0; a < 4; a++)
#pragma unroll
        for (int b = 0; b < 4; b++) acc[a][b] = 0.f;

    const int m  = tid >> 2;
    const int kb = (tid & 3) << 4;

    for (int k0 = 0; k0 < DIN; k0 += 64) {
#pragma unroll
        for (int q = 0; q < 4; q++) {
            float4 va = *(const float4*)(x   + (size_t)(t0 + m) * DIN + k0 + kb + q * 4);
            As[kb + q*4 + 0][m] = va.x; As[kb + q*4 + 1][m] = va.y;
            As[kb + q*4 + 2][m] = va.z; As[kb + q*4 + 3][m] = va.w;
            float4 vb = *(const float4*)(Wih + (size_t)(r0 + m) * DIN + k0 + kb + q * 4);
            Bs[kb + q*4 + 0][m] = vb.x; Bs[kb + q*4 + 1][m] = vb.y;
            Bs[kb + q*4 + 2][m] = vb.z; Bs[kb + q*4 + 3][m] = vb.w;
        }
        __syncthreads();
#pragma unroll
        for (int kk = 0; kk < 64; kk++) {
            float4 a4 = *(const float4*)&As[kk][ty * 4];
            float4 b4 = *(const float4*)&Bs[kk][tx * 4];
            acc[0][0] = fmaf(a4.x, b4.x, acc[0][0]);
            acc[0][1] = fmaf(a4.x, b4.y, acc[0][1]);
            acc[0][2] = fmaf(a4.x, b4.z, acc[0][2]);
            acc[0][3] = fmaf(a4.x, b4.w, acc[0][3]);
            acc[1][0] = fmaf(a4.y, b4.x, acc[1][0]);
            acc[1][1] = fmaf(a4.y, b4.y, acc[1][1]);
            acc[1][2] = fmaf(a4.y, b4.z, acc[1][2]);
            acc[1][3] = fmaf(a4.y, b4.w, acc[1][3]);
            acc[2][0] = fmaf(a4.z, b4.x, acc[2][0]);
            acc[2][1] = fmaf(a4.z, b4.y, acc[2][1]);
            acc[2][2] = fmaf(a4.z, b4.z, acc[2][2]);
            acc[2][3] = fmaf(a4.z, b4.w, acc[2][3]);
            acc[3][0] = fmaf(a4.w, b4.x, acc[3][0]);
            acc[3][1] = fmaf(a4.w, b4.y, acc[3][1]);
            acc[3][2] = fmaf(a4.w, b4.z, acc[3][2]);
            acc[3][3] = fmaf(a4.w, b4.w, acc[3][3]);
        }
        __syncthreads();
    }

    const int r = r0 + tx * 4;
    float b0 = bih[r + 0] + bhh[r + 0];
    float b1 = bih[r + 1] + bhh[r + 1];
    float b2 = bih[r + 2] + bhh[r + 2];
    float b3 = bih[r + 3] + bhh[r + 3];
#pragma unroll
    for (int mi = 0; mi < 4; mi++) {
        float4 o;
        o.x = acc[mi][0] + b0; o.y = acc[mi][1] + b1;
        o.z = acc[mi][2] + b2; o.w = acc[mi][3] + b3;
        *(float4*)(g_xg + (size_t)(t0 + ty * 4 + mi) * H4 + r) = o;
    }
}

// ---------------- persistent LSTM recurrence --------------------------------
__device__ __forceinline__ float sigm(float v) {
    return 1.f / (1.f + __expf(-v));
}
// tanh via sigmoid identity: short EX2/RCP chain, ~1e-6 accurate
__device__ __forceinline__ float tanh_fast(float v) {
    return fmaf(2.f, sigm(2.f * v), -1.f);
}

// bf16 pair (packed in u32: elem k low, elem k+1 high) expanded via cheap ALU
#define BF_LO(u) __uint_as_float((u) << 16)
#define BF_HI(u) __uint_as_float((u) & 0xffff0000u)

// accumulate 8 weights (uint4) * 8 h values (2x float4)
#define ACC8(A, W, H0, H1) do {                     \
    A = fmaf(BF_LO((W).x), (H0).x, A);              \
    A = fmaf(BF_HI((W).x), (H0).y, A);              \
    A = fmaf(BF_LO((W).y), (H0).z, A);              \
    A = fmaf(BF_HI((W).y), (H0).w, A);              \
    A = fmaf(BF_LO((W).z), (H1).x, A);              \
    A = fmaf(BF_HI((W).z), (H1).y, A);              \
    A = fmaf(BF_LO((W).w), (H1).z, A);              \
    A = fmaf(BF_HI((W).w), (H1).w, A);              \
} while (0)

__global__ void __launch_bounds__(NTHR, 1)
lstm_kernel(const float* __restrict__ cprev, float* __restrict__ dout)
{
    // SMEM: all gate-row weights, uint4 layout ((w*8+i)*4+gate)*32 + l
    extern __shared__ uint4 sw[];   // 14*1024 uint4 = 229376 B max

    const int cta = blockIdx.x;
    int jbase, nj;
    if (cta < 124) { nj = 14; jbase = cta * 14; }
    else           { nj = 13; jbase = 1736 + (cta - 124) * 13; }

    const int w = threadIdx.x >> 5;
    const int l = threadIdx.x & 31;
    const bool active = (w < nj);
    const int j = jbase + w;

    // ---- stage all weights into SMEM
    const int tot = nj * 1024;   // uint4 per CTA
    for (int idx = threadIdx.x; idx < tot; idx += NTHR) {
        int l2   = idx & 31;
        int gate = (idx >> 5) & 3;
        int i    = (idx >> 7) & 7;
        int ww   = idx >> 10;
        int row  = gate * H + jbase + ww;
        sw[idx] = ((const uint4*)g_Whh)[(size_t)row * 256 + i * 32 + l2];
    }

    float c = 0.f, hkeep = 0.f;
    if (active && l == 0) c = cprev[j];
    __syncthreads();

    const uint4* wq = sw + (size_t)w * 1024 + l;   // + (i*4+gate)*32

    for (int t = 0; t < SEQ; t++) {
        // ---- prefetch xg (independent; hides DRAM latency)
        float xgv = 0.f;
        if (active && l < 4)
            xgv = __ldg(&g_xg[(size_t)t * H4 + l * H + j]);

        // ---- lane 0: poll barrier, then fence (CCTL.IVALL flushes stale L1)
        if (threadIdx.x == 0) {
            if (t > 0) {
                const unsigned target = (unsigned)t * (unsigned)NCTA;
                unsigned v;
                do {
                    asm volatile("ld.acquire.gpu.global.u32 %0, [%1];"
                                 : "=r"(v) : "l"(&g_bar) : "memory");
                } while (v < target);
            }
            __threadfence();   // emits CCTL.IVALL: L1 coherent with fresh h
        }
        __syncthreads();                         // sync A: h(t) readable

        float a0 = 0.f, a1 = 0.f, a2 = 0.f, a3 = 0.f;
        if (active) {
            const float* hb = g_hbuf[t & 1];
#pragma unroll
            for (int i = 0; i < 8; i++) {
                // plain L1-cached loads: 1st toucher misses, 13 warps hit
                float4 h0 = *(const float4*)(hb + i * 256 + l * 8);
                float4 h1 = *(const float4*)(hb + i * 256 + l * 8 + 4);
                uint4 w0 = wq[(i * 4 + 0) * 32];
                uint4 w1 = wq[(i * 4 + 1) * 32];
                uint4 w2 = wq[(i * 4 + 2) * 32];
                uint4 w3 = wq[(i * 4 + 3) * 32];
                ACC8(a0, w0, h0, h1);
                ACC8(a1, w1, h0, h1);
                ACC8(a2, w2, h0, h1);
                ACC8(a3, w3, h0, h1);
            }
            // butterfly reduce: every lane ends with all four sums
#pragma unroll
            for (int off = 16; off > 0; off >>= 1) {
                a0 += __shfl_xor_sync(0xffffffffu, a0, off);
                a1 += __shfl_xor_sync(0xffffffffu, a1, off);
                a2 += __shfl_xor_sync(0xffffffffu, a2, off);
                a3 += __shfl_xor_sync(0xffffffffu, a3, off);
            }
            // lanes 0-3 each compute one gate activation
            float acts = 0.f;
            if (l < 4) {
                float z = (l == 0) ? a0 : (l == 1) ? a1 : (l == 2) ? a2 : a3;
                z += xgv;                       // lane g owns xg for gate g
                float m = (l == 2) ? 2.f : 1.f;
                float s = (l == 2) ? 2.f : 1.f;
                float b = (l == 2) ? -1.f : 0.f;
                acts = fmaf(s, sigm(m * z), b);
            }
            float ig = __shfl_sync(0xffffffffu, acts, 0);
            float fg = __shfl_sync(0xffffffffu, acts, 1);
            float gg = __shfl_sync(0xffffffffu, acts, 2);
            float og = __shfl_sync(0xffffffffu, acts, 3);
            if (l == 0) {
                c = fg * c + ig * gg;
                float hn = og * tanh_fast(c);
                hkeep = hn;
                g_hbuf[(t + 1) & 1][j] = hn;
                g_hs[(size_t)t * H + j] = hn;
            }
        }

        __syncthreads();                         // sync B: all reads+writes done
        if (threadIdx.x == 0)
            asm volatile("red.release.gpu.global.add.u32 [%0], %1;"
                         :: "l"(&g_bar), "r"(1u) : "memory");
    }

    if (active && l == 0) {
        dout[OUT_BASE + j]     = hkeep;   // hT
        dout[OUT_BASE + H + j] = c;       // cT
    }
}

// ---------------- output FC: out = sigmoid(hs @ W_fc^T + b_fc) --------------
__global__ void fc_kernel(const float* __restrict__ bfc, float* __restrict__ out)
{
    const int gw = (blockIdx.x * blockDim.x + threadIdx.x) >> 5;  // 0..4095
    const int l  = threadIdx.x & 31;
    const int t0 = gw * 2;

    float ax0 = 0.f, ay0 = 0.f, ax1 = 0.f, ay1 = 0.f;
    const float* hs0 = g_hs + (size_t)t0 * H;

#pragma unroll 8
    for (int k = 0; k < H; k++) {
        float2 wv = *(const float2*)(g_WfcT + k * DOUT + 2 * l);
        float h0 = __ldg(hs0 + k);
        float h1 = __ldg(hs0 + H + k);
        ax0 = fmaf(h0, wv.x, ax0); ay0 = fmaf(h0, wv.y, ay0);
        ax1 = fmaf(h1, wv.x, ax1); ay1 = fmaf(h1, wv.y, ay1);
    }
    const float bx = bfc[2 * l], by = bfc[2 * l + 1];
    float2 o;
    o.x = sigm(ax0 + bx); o.y = sigm(ay0 + by);
    *(float2*)(out + (size_t)(t0 + 0) * DOUT + 2 * l) = o;
    o.x = sigm(ax1 + bx); o.y = sigm(ay1 + by);
    *(float2*)(out + (size_t)(t0 + 1) * DOUT + 2 * l) = o;
}

// ---------------- launch -----------------------------------------------------
extern "C" void kernel_launch(void* const* d_in, const int* in_sizes, int n_in,
                              void* d_out, int out_size)
{
    const float* x     = (const float*)d_in[0];
    const float* hprev = (const float*)d_in[1];
    const float* cprev = (const float*)d_in[2];
    const float* Wih   = (const float*)d_in[3];
    const float* Whh   = (const float*)d_in[4];
    const float* bih   = (const float*)d_in[5];
    const float* bhh   = (const float*)d_in[6];
    const float* Wfc   = (const float*)d_in[7];
    const float* bfc   = (const float*)d_in[8];
    float* out = (float*)d_out;

    const int smem_bytes = 14 * 1024 * 16;   // 229376 B
    cudaFuncSetAttribute(lstm_kernel,
                         cudaFuncAttributeMaxDynamicSharedMemorySize, smem_bytes);

    prep_kernel<<<4096, 256>>>(Whh, hprev, Wfc);

    dim3 gg(H4 / 64, SEQ / 64);
    xg_kernel<<<gg, 256>>>(x, Wih, bih, bhh);

    lstm_kernel<<<NCTA, NTHR, smem_bytes>>>(cprev, out);

    fc_kernel<<<512, 256>>>(bfc, out);
}

// round 14
// speedup vs baseline: 1.1811x; 1.1811x over previous
#include <cuda_runtime.h>
#include <cuda_bf16.h>

#define SEQ   8192
#define DIN   256
#define H     2048
#define H4    8192
#define DOUT  64
#define NCTA  148
#define NTHR  448   // 14 warps
#define OUT_BASE (SEQ * DOUT)   // 524288

#define SW_ITERS 12   // k-iterations (of 16) whose weights live in SMEM
#define RW_ITERS 4    // k-iterations whose weights live in registers

// ---------------- device scratch (allowed: __device__ globals) --------------
__device__ __nv_bfloat16 g_Whh[(size_t)H4 * H]; // 33.5 MB bf16 W_hh
__device__ float   g_xg [(size_t)SEQ * H4];     // 256 MB  x @ W_ih^T + b
__device__ float   g_hs [(size_t)SEQ * H];      // 64 MB   h history
__device__ float   g_hbuf[2][H];                // double-buffered h
__device__ float   g_WfcT[H * DOUT];            // W_fc transposed [k][d]
__device__ unsigned g_bar;                      // cumulative grid barrier

// ---------------- prep: bf16 convert, transpose, init ----------------------
__global__ void prep_kernel(const float* __restrict__ Whh,
                            const float* __restrict__ hprev,
                            const float* __restrict__ Wfc)
{
    size_t stride = (size_t)gridDim.x * blockDim.x;
    size_t i0 = (size_t)blockIdx.x * blockDim.x + threadIdx.x;
    const size_t npair = (size_t)H4 * H / 2;
    for (size_t p = i0; p < npair; p += stride) {
        float2 v = ((const float2*)Whh)[p];
        ((__nv_bfloat162*)g_Whh)[p] = __floats2bfloat162_rn(v.x, v.y);
    }
    for (size_t i = i0; i < H; i += stride)
        g_hbuf[0][i] = hprev[i];
    for (size_t i = i0; i < (size_t)H * DOUT; i += stride) {
        int d = (int)(i & (DOUT - 1));
        int k = (int)(i >> 6);
        g_WfcT[i] = Wfc[(size_t)d * H + k];
    }
    if (i0 == 0) g_bar = 0u;
}

// ---------------- xg GEMM: xg[t][r] = sum_k x[t][k] W_ih[r][k] + b ----------
__global__ void xg_kernel(const float* __restrict__ x,
                          const float* __restrict__ Wih,
                          const float* __restrict__ bih,
                          const float* __restrict__ bhh)
{
    __shared__ float As[64][68];
    __shared__ float Bs[64][68];
    const int tid = threadIdx.x;
    const int tx = tid & 15, ty = tid >> 4;
    const int t0 = blockIdx.y * 64, r0 = blockIdx.x * 64;

    float acc[4][4];
#pragma unroll
    for (int a = 0; a < 4; a++)
#pragma unroll
        for (int b = 0; b < 4; b++) acc[a][b] = 0.f;

    const int m  = tid >> 2;
    const int kb = (tid & 3) << 4;

    for (int k0 = 0; k0 < DIN; k0 += 64) {
#pragma unroll
        for (int q = 0; q < 4; q++) {
            float4 va = *(const float4*)(x   + (size_t)(t0 + m) * DIN + k0 + kb + q * 4);
            As[kb + q*4 + 0][m] = va.x; As[kb + q*4 + 1][m] = va.y;
            As[kb + q*4 + 2][m] = va.z; As[kb + q*4 + 3][m] = va.w;
            float4 vb = *(const float4*)(Wih + (size_t)(r0 + m) * DIN + k0 + kb + q * 4);
            Bs[kb + q*4 + 0][m] = vb.x; Bs[kb + q*4 + 1][m] = vb.y;
            Bs[kb + q*4 + 2][m] = vb.z; Bs[kb + q*4 + 3][m] = vb.w;
        }
        __syncthreads();
#pragma unroll
        for (int kk = 0; kk < 64; kk++) {
            float4 a4 = *(const float4*)&As[kk][ty * 4];
            float4 b4 = *(const float4*)&Bs[kk][tx * 4];
            acc[0][0] = fmaf(a4.x, b4.x, acc[0][0]);
            acc[0][1] = fmaf(a4.x, b4.y, acc[0][1]);
            acc[0][2] = fmaf(a4.x, b4.z, acc[0][2]);
            acc[0][3] = fmaf(a4.x, b4.w, acc[0][3]);
            acc[1][0] = fmaf(a4.y, b4.x, acc[1][0]);
            acc[1][1] = fmaf(a4.y, b4.y, acc[1][1]);
            acc[1][2] = fmaf(a4.y, b4.z, acc[1][2]);
            acc[1][3] = fmaf(a4.y, b4.w, acc[1][3]);
            acc[2][0] = fmaf(a4.z, b4.x, acc[2][0]);
            acc[2][1] = fmaf(a4.z, b4.y, acc[2][1]);
            acc[2][2] = fmaf(a4.z, b4.z, acc[2][2]);
            acc[2][3] = fmaf(a4.z, b4.w, acc[2][3]);
            acc[3][0] = fmaf(a4.w, b4.x, acc[3][0]);
            acc[3][1] = fmaf(a4.w, b4.y, acc[3][1]);
            acc[3][2] = fmaf(a4.w, b4.z, acc[3][2]);
            acc[3][3] = fmaf(a4.w, b4.w, acc[3][3]);
        }
        __syncthreads();
    }

    const int r = r0 + tx * 4;
    float b0 = bih[r + 0] + bhh[r + 0];
    float b1 = bih[r + 1] + bhh[r + 1];
    float b2 = bih[r + 2] + bhh[r + 2];
    float b3 = bih[r + 3] + bhh[r + 3];
#pragma unroll
    for (int mi = 0; mi < 4; mi++) {
        float4 o;
        o.x = acc[mi][0] + b0; o.y = acc[mi][1] + b1;
        o.z = acc[mi][2] + b2; o.w = acc[mi][3] + b3;
        *(float4*)(g_xg + (size_t)(t0 + ty * 4 + mi) * H4 + r) = o;
    }
}

// ---------------- persistent LSTM recurrence --------------------------------
__device__ __forceinline__ float sigm(float v) {
    return 1.f / (1.f + __expf(-v));
}
// tanh via sigmoid identity: short EX2/RCP chain, ~1e-6 accurate
__device__ __forceinline__ float tanh_fast(float v) {
    return fmaf(2.f, sigm(2.f * v), -1.f);
}

// bf16 pair (packed in u32: elem k low, elem k+1 high) expanded via cheap ALU
#define BF_LO(u) __uint_as_float((u) << 16)
#define BF_HI(u) __uint_as_float((u) & 0xffff0000u)

// accumulate 4 weights (uint2 = 4 bf16) * 4 h values (float4)
#define ACC4(A, W, HV) do {                         \
    A = fmaf(BF_LO((W).x), (HV).x, A);              \
    A = fmaf(BF_HI((W).x), (HV).y, A);              \
    A = fmaf(BF_LO((W).y), (HV).z, A);              \
    A = fmaf(BF_HI((W).y), (HV).w, A);              \
} while (0)

__global__ void __launch_bounds__(NTHR, 1)
lstm_kernel(const float* __restrict__ cprev, float* __restrict__ dout)
{
    // SMEM: [0, 172032) bf16 weights as uint2; [172032, 180224) staged h
    extern __shared__ unsigned char smem_raw[];
    uint2* sw  = (uint2*)smem_raw;
    float* shh = (float*)(smem_raw + 14 * SW_ITERS * 4 * 32 * 8);

    const int cta = blockIdx.x;
    int jbase, nj;
    if (cta < 124) { nj = 14; jbase = cta * 14; }
    else           { nj = 13; jbase = 1736 + (cta - 124) * 13; }

    const int w = threadIdx.x >> 5;
    const int l = threadIdx.x & 31;
    const bool active = (w < nj);
    const int j = jbase + w;

    // ---- stage SMEM weights: layout ((w*SW + i)*4 + row)*32 + l, uint2 each
    const int tot = nj * SW_ITERS * 4 * 32;
    for (int idx = threadIdx.x; idx < tot; idx += NTHR) {
        int l2  = idx & 31;
        int row = (idx >> 5) & 3;
        int q   = idx >> 7;
        int i   = q % SW_ITERS;
        int ww  = q / SW_ITERS;
        size_t src = ((size_t)(row * H + jbase + ww) * 2048 + (size_t)i * 128 + l2 * 4) >> 2;
        sw[idx] = ((const uint2*)g_Whh)[src];
    }

    // ---- register-resident weights: iterations SW_ITERS..15
    uint2 rw[RW_ITERS][4];
    if (active) {
#pragma unroll
        for (int i2 = 0; i2 < RW_ITERS; i2++)
#pragma unroll
            for (int r = 0; r < 4; r++)
                rw[i2][r] = ((const uint2*)g_Whh)[
                    ((size_t)(r * H + j) * 2048 + (size_t)(SW_ITERS + i2) * 128 + l * 4) >> 2];
    }

    float c = 0.f, hkeep = 0.f;
    if (active && l == 0) c = cprev[j];
    __syncthreads();

    const uint2* wp = sw + (size_t)w * SW_ITERS * 4 * 32 + l;

    for (int t = 0; t < SEQ; t++) {
        // ---- stage h into SMEM (all threads; L1-bypassing for coherence)
        const float4* hb4 = (const float4*)g_hbuf[t & 1];
        for (int idx = threadIdx.x; idx < 512; idx += NTHR)
            ((float4*)shh)[idx] = __ldcg(hb4 + idx);

        // ---- prefetch xg (independent; overlaps with compute)
        float xgv = 0.f;
        if (active && l < 4)
            xgv = __ldg(&g_xg[(size_t)t * H4 + l * H + j]);
        __syncthreads();                         // sync #1: shh ready

        float a0 = 0.f, a1 = 0.f, a2 = 0.f, a3 = 0.f;
        if (active) {
#pragma unroll
            for (int i = 0; i < SW_ITERS; i++) {
                float4 hv = *(const float4*)(shh + i * 128 + l * 4);
                uint2 w0 = wp[i * 128 +  0];
                uint2 w1 = wp[i * 128 + 32];
                uint2 w2 = wp[i * 128 + 64];
                uint2 w3 = wp[i * 128 + 96];
                ACC4(a0, w0, hv);
                ACC4(a1, w1, hv);
                ACC4(a2, w2, hv);
                ACC4(a3, w3, hv);
            }
#pragma unroll
            for (int i2 = 0; i2 < RW_ITERS; i2++) {
                float4 hv = *(const float4*)(shh + (SW_ITERS + i2) * 128 + l * 4);
                ACC4(a0, rw[i2][0], hv);
                ACC4(a1, rw[i2][1], hv);
                ACC4(a2, rw[i2][2], hv);
                ACC4(a3, rw[i2][3], hv);
            }
            // fold xg in BEFORE reduction: lane g owns xg for gate g
            a0 += (l == 0) ? xgv : 0.f;
            a1 += (l == 1) ? xgv : 0.f;
            a2 += (l == 2) ? xgv : 0.f;
            a3 += (l == 3) ? xgv : 0.f;
#pragma unroll
            for (int off = 16; off > 0; off >>= 1) {
                a0 += __shfl_down_sync(0xffffffffu, a0, off);
                a1 += __shfl_down_sync(0xffffffffu, a1, off);
                a2 += __shfl_down_sync(0xffffffffu, a2, off);
                a3 += __shfl_down_sync(0xffffffffu, a3, off);
            }
            if (l == 0) {
                float ig = sigm(a0);
                float fg = sigm(a1);
                float gg = tanh_fast(a2);
                float og = sigm(a3);
                c = fg * c + ig * gg;
                float hn = og * tanh_fast(c);
                hkeep = hn;
                g_hbuf[(t + 1) & 1][j] = hn;
                g_hs[(size_t)t * H + j] = hn;
            }
        }

        __syncthreads();                         // sync #2: all writes done
        if (threadIdx.x == 0) {
            asm volatile("red.release.gpu.global.add.u32 [%0], %1;"
                         :: "l"(&g_bar), "r"(1u) : "memory");
            const unsigned target = (unsigned)(t + 1) * (unsigned)NCTA;
            unsigned v;
            do {
                asm volatile("ld.acquire.gpu.global.u32 %0, [%1];"
                             : "=r"(v) : "l"(&g_bar) : "memory");
            } while (v < target);
        }
        __syncthreads();                         // sync #3: release whole CTA
    }

    if (active && l == 0) {
        dout[OUT_BASE + j]     = hkeep;   // hT
        dout[OUT_BASE + H + j] = c;       // cT
    }
}

// ---------------- output FC: out = sigmoid(hs @ W_fc^T + b_fc) --------------
__global__ void fc_kernel(const float* __restrict__ bfc, float* __restrict__ out)
{
    const int gw = (blockIdx.x * blockDim.x + threadIdx.x) >> 5;  // 0..4095
    const int l  = threadIdx.x & 31;
    const int t0 = gw * 2;

    float ax0 = 0.f, ay0 = 0.f, ax1 = 0.f, ay1 = 0.f;
    const float* hs0 = g_hs + (size_t)t0 * H;

#pragma unroll 8
    for (int k = 0; k < H; k++) {
        float2 wv = *(const float2*)(g_WfcT + k * DOUT + 2 * l);
        float h0 = __ldg(hs0 + k);
        float h1 = __ldg(hs0 + H + k);
        ax0 = fmaf(h0, wv.x, ax0); ay0 = fmaf(h0, wv.y, ay0);
        ax1 = fmaf(h1, wv.x, ax1); ay1 = fmaf(h1, wv.y, ay1);
    }
    const float bx = bfc[2 * l], by = bfc[2 * l + 1];
    float2 o;
    o.x = sigm(ax0 + bx); o.y = sigm(ay0 + by);
    *(float2*)(out + (size_t)(t0 + 0) * DOUT + 2 * l) = o;
    o.x = sigm(ax1 + bx); o.y = sigm(ay1 + by);
    *(float2*)(out + (size_t)(t0 + 1) * DOUT + 2 * l) = o;
}

// ---------------- launch -----------------------------------------------------
extern "C" void kernel_launch(void* const* d_in, const int* in_sizes, int n_in,
                              void* d_out, int out_size)
{
    const float* x     = (const float*)d_in[0];
    const float* hprev = (const float*)d_in[1];
    const float* cprev = (const float*)d_in[2];
    const float* Wih   = (const float*)d_in[3];
    const float* Whh   = (const float*)d_in[4];
    const float* bih   = (const float*)d_in[5];
    const float* bhh   = (const float*)d_in[6];
    const float* Wfc   = (const float*)d_in[7];
    const float* bfc   = (const float*)d_in[8];
    float* out = (float*)d_out;

    const int smem_bytes = 14 * SW_ITERS * 4 * 32 * 8 + 2048 * 4;  // 180224
    cudaFuncSetAttribute(lstm_kernel,
                         cudaFuncAttributeMaxDynamicSharedMemorySize, smem_bytes);

    prep_kernel<<<4096, 256>>>(Whh, hprev, Wfc);

    dim3 gg(H4 / 64, SEQ / 64);
    xg_kernel<<<gg, 256>>>(x, Wih, bih, bhh);

    lstm_kernel<<<NCTA, NTHR, smem_bytes>>>(cprev, out);

    fc_kernel<<<512, 256>>>(bfc, out);
}

// round 15
// speedup vs baseline: 1.1831x; 1.0017x over previous
#include <cuda_runtime.h>
#include <cuda_bf16.h>

#define SEQ   8192
#define DIN   256
#define H     2048
#define H4    8192
#define DOUT  64
#define NCTA  148
#define NTHR  448   // 14 warps
#define OUT_BASE (SEQ * DOUT)   // 524288

#define SW_ITERS 12   // k-iterations (of 16) whose weights live in SMEM
#define RW_ITERS 4    // k-iterations whose weights live in registers

// ---------------- device scratch (allowed: __device__ globals) --------------
__device__ __nv_bfloat16 g_Whh[(size_t)H4 * H]; // 33.5 MB bf16 W_hh
__device__ float   g_xg [(size_t)SEQ * H4];     // 256 MB  x @ W_ih^T + b
__device__ float   g_hs [(size_t)SEQ * H];      // 64 MB   h history
__device__ float   g_hbuf[2][H];                // double-buffered h
__device__ float   g_WfcT[H * DOUT];            // W_fc transposed [k][d]
__device__ unsigned g_bar;                      // cumulative grid barrier

// ---------------- prep: bf16 convert, transpose, init ----------------------
__global__ void prep_kernel(const float* __restrict__ Whh,
                            const float* __restrict__ hprev,
                            const float* __restrict__ Wfc)
{
    size_t stride = (size_t)gridDim.x * blockDim.x;
    size_t i0 = (size_t)blockIdx.x * blockDim.x + threadIdx.x;
    const size_t npair = (size_t)H4 * H / 2;
    for (size_t p = i0; p < npair; p += stride) {
        float2 v = ((const float2*)Whh)[p];
        ((__nv_bfloat162*)g_Whh)[p] = __floats2bfloat162_rn(v.x, v.y);
    }
    for (size_t i = i0; i < H; i += stride)
        g_hbuf[0][i] = hprev[i];
    for (size_t i = i0; i < (size_t)H * DOUT; i += stride) {
        int d = (int)(i & (DOUT - 1));
        int k = (int)(i >> 6);
        g_WfcT[i] = Wfc[(size_t)d * H + k];
    }
    if (i0 == 0) g_bar = 0u;
}

// ---------------- xg GEMM: xg[t][r] = sum_k x[t][k] W_ih[r][k] + b ----------
__global__ void xg_kernel(const float* __restrict__ x,
                          const float* __restrict__ Wih,
                          const float* __restrict__ bih,
                          const float* __restrict__ bhh)
{
    __shared__ float As[64][68];
    __shared__ float Bs[64][68];
    const int tid = threadIdx.x;
    const int tx = tid & 15, ty = tid >> 4;
    const int t0 = blockIdx.y * 64, r0 = blockIdx.x * 64;

    float acc[4][4];
#pragma unroll
    for (int a = 0; a < 4; a++)
#pragma unroll
        for (int b = 0; b < 4; b++) acc[a][b] = 0.f;

    const int m  = tid >> 2;
    const int kb = (tid & 3) << 4;

    for (int k0 = 0; k0 < DIN; k0 += 64) {
#pragma unroll
        for (int q = 0; q < 4; q++) {
            float4 va = *(const float4*)(x   + (size_t)(t0 + m) * DIN + k0 + kb + q * 4);
            As[kb + q*4 + 0][m] = va.x; As[kb + q*4 + 1][m] = va.y;
            As[kb + q*4 + 2][m] = va.z; As[kb + q*4 + 3][m] = va.w;
            float4 vb = *(const float4*)(Wih + (size_t)(r0 + m) * DIN + k0 + kb + q * 4);
            Bs[kb + q*4 + 0][m] = vb.x; Bs[kb + q*4 + 1][m] = vb.y;
            Bs[kb + q*4 + 2][m] = vb.z; Bs[kb + q*4 + 3][m] = vb.w;
        }
        __syncthreads();
#pragma unroll
        for (int kk = 0; kk < 64; kk++) {
            float4 a4 = *(const float4*)&As[kk][ty * 4];
            float4 b4 = *(const float4*)&Bs[kk][tx * 4];
            acc[0][0] = fmaf(a4.x, b4.x, acc[0][0]);
            acc[0][1] = fmaf(a4.x, b4.y, acc[0][1]);
            acc[0][2] = fmaf(a4.x, b4.z, acc[0][2]);
            acc[0][3] = fmaf(a4.x, b4.w, acc[0][3]);
            acc[1][0] = fmaf(a4.y, b4.x, acc[1][0]);
            acc[1][1] = fmaf(a4.y, b4.y, acc[1][1]);
            acc[1][2] = fmaf(a4.y, b4.z, acc[1][2]);
            acc[1][3] = fmaf(a4.y, b4.w, acc[1][3]);
            acc[2][0] = fmaf(a4.z, b4.x, acc[2][0]);
            acc[2][1] = fmaf(a4.z, b4.y, acc[2][1]);
            acc[2][2] = fmaf(a4.z, b4.z, acc[2][2]);
            acc[2][3] = fmaf(a4.z, b4.w, acc[2][3]);
            acc[3][0] = fmaf(a4.w, b4.x, acc[3][0]);
            acc[3][1] = fmaf(a4.w, b4.y, acc[3][1]);
            acc[3][2] = fmaf(a4.w, b4.z, acc[3][2]);
            acc[3][3] = fmaf(a4.w, b4.w, acc[3][3]);
        }
        __syncthreads();
    }

    const int r = r0 + tx * 4;
    float b0 = bih[r + 0] + bhh[r + 0];
    float b1 = bih[r + 1] + bhh[r + 1];
    float b2 = bih[r + 2] + bhh[r + 2];
    float b3 = bih[r + 3] + bhh[r + 3];
#pragma unroll
    for (int mi = 0; mi < 4; mi++) {
        float4 o;
        o.x = acc[mi][0] + b0; o.y = acc[mi][1] + b1;
        o.z = acc[mi][2] + b2; o.w = acc[mi][3] + b3;
        *(float4*)(g_xg + (size_t)(t0 + ty * 4 + mi) * H4 + r) = o;
    }
}

// ---------------- persistent LSTM recurrence --------------------------------
__device__ __forceinline__ float sigm(float v) {
    return 1.f / (1.f + __expf(-v));
}
// tanh via sigmoid identity: short EX2/RCP chain, ~1e-6 accurate
__device__ __forceinline__ float tanh_fast(float v) {
    return fmaf(2.f, sigm(2.f * v), -1.f);
}

// packed f32x2 FMA: ACC(2xf32) += {bf_lo(WU), bf_hi(WU)} * HP(2xf32)
// bf16 pair packed in u32 (elem 2k low half, elem 2k+1 high half);
// lo/hi expansion is exact (bf16 = top 16 bits of f32).
#define FMA2(ACC, WU, HP) do {                                          \
    unsigned _lo = (WU) << 16;                                          \
    unsigned _hi = (WU) & 0xffff0000u;                                  \
    asm("{\n\t"                                                         \
        ".reg .b64 wp;\n\t"                                             \
        "mov.b64 wp, {%1,%2};\n\t"                                      \
        "fma.rn.f32x2 %0, wp, %3, %0;\n\t"                              \
        "}" : "+l"(ACC) : "r"(_lo), "r"(_hi), "l"(HP));                 \
} while (0)

// one uint2 (4 bf16 weights) against one packed h quad (2x u64 = 4 floats)
#define PACC(A, W, HP01, HP23) do {                                     \
    FMA2(A, (W).x, HP01);                                               \
    FMA2(A, (W).y, HP23);                                               \
} while (0)

__global__ void __launch_bounds__(NTHR, 1)
lstm_kernel(const float* __restrict__ cprev, float* __restrict__ dout)
{
    // SMEM: [0, 172032) bf16 weights as uint2; [172032, 180224) staged h
    extern __shared__ unsigned char smem_raw[];
    uint2* sw  = (uint2*)smem_raw;
    float* shh = (float*)(smem_raw + 14 * SW_ITERS * 4 * 32 * 8);

    const int cta = blockIdx.x;
    int jbase, nj;
    if (cta < 124) { nj = 14; jbase = cta * 14; }
    else           { nj = 13; jbase = 1736 + (cta - 124) * 13; }

    const int w = threadIdx.x >> 5;
    const int l = threadIdx.x & 31;
    const bool active = (w < nj);
    const int j = jbase + w;

    // ---- stage SMEM weights: layout ((w*SW + i)*4 + row)*32 + l, uint2 each
    const int tot = nj * SW_ITERS * 4 * 32;
    for (int idx = threadIdx.x; idx < tot; idx += NTHR) {
        int l2  = idx & 31;
        int row = (idx >> 5) & 3;
        int q   = idx >> 7;
        int i   = q % SW_ITERS;
        int ww  = q / SW_ITERS;
        size_t src = ((size_t)(row * H + jbase + ww) * 2048 + (size_t)i * 128 + l2 * 4) >> 2;
        sw[idx] = ((const uint2*)g_Whh)[src];
    }

    // ---- register-resident weights: iterations SW_ITERS..15
    uint2 rw[RW_ITERS][4];
    if (active) {
#pragma unroll
        for (int i2 = 0; i2 < RW_ITERS; i2++)
#pragma unroll
            for (int r = 0; r < 4; r++)
                rw[i2][r] = ((const uint2*)g_Whh)[
                    ((size_t)(r * H + j) * 2048 + (size_t)(SW_ITERS + i2) * 128 + l * 4) >> 2];
    }

    float c = 0.f, hkeep = 0.f;
    if (active && l == 0) c = cprev[j];
    __syncthreads();

    const uint2* wp = sw + (size_t)w * SW_ITERS * 4 * 32 + l;

    for (int t = 0; t < SEQ; t++) {
        // ---- stage h into SMEM (all threads; L1-bypassing for coherence)
        const float4* hb4 = (const float4*)g_hbuf[t & 1];
        for (int idx = threadIdx.x; idx < 512; idx += NTHR)
            ((float4*)shh)[idx] = __ldcg(hb4 + idx);

        // ---- prefetch xg (independent; overlaps with compute)
        float xgv = 0.f;
        if (active && l < 4)
            xgv = __ldg(&g_xg[(size_t)t * H4 + l * H + j]);
        __syncthreads();                         // sync #1: shh ready

        unsigned long long p0 = 0ull, p1 = 0ull, p2 = 0ull, p3 = 0ull;
        float a0 = 0.f, a1 = 0.f, a2 = 0.f, a3 = 0.f;
        if (active) {
#pragma unroll
            for (int i = 0; i < SW_ITERS; i++) {
                ulonglong2 hq = *(const ulonglong2*)(shh + i * 128 + l * 4);
                uint2 w0 = wp[i * 128 +  0];
                uint2 w1 = wp[i * 128 + 32];
                uint2 w2 = wp[i * 128 + 64];
                uint2 w3 = wp[i * 128 + 96];
                PACC(p0, w0, hq.x, hq.y);
                PACC(p1, w1, hq.x, hq.y);
                PACC(p2, w2, hq.x, hq.y);
                PACC(p3, w3, hq.x, hq.y);
            }
#pragma unroll
            for (int i2 = 0; i2 < RW_ITERS; i2++) {
                ulonglong2 hq = *(const ulonglong2*)(shh + (SW_ITERS + i2) * 128 + l * 4);
                PACC(p0, rw[i2][0], hq.x, hq.y);
                PACC(p1, rw[i2][1], hq.x, hq.y);
                PACC(p2, rw[i2][2], hq.x, hq.y);
                PACC(p3, rw[i2][3], hq.x, hq.y);
            }
            // unpack packed accumulators: a = lo + hi
            {
                unsigned lo, hi;
                asm("mov.b64 {%0,%1}, %2;" : "=r"(lo), "=r"(hi) : "l"(p0));
                a0 = __uint_as_float(lo) + __uint_as_float(hi);
                asm("mov.b64 {%0,%1}, %2;" : "=r"(lo), "=r"(hi) : "l"(p1));
                a1 = __uint_as_float(lo) + __uint_as_float(hi);
                asm("mov.b64 {%0,%1}, %2;" : "=r"(lo), "=r"(hi) : "l"(p2));
                a2 = __uint_as_float(lo) + __uint_as_float(hi);
                asm("mov.b64 {%0,%1}, %2;" : "=r"(lo), "=r"(hi) : "l"(p3));
                a3 = __uint_as_float(lo) + __uint_as_float(hi);
            }
            // fold xg in BEFORE reduction: lane g owns xg for gate g
            a0 += (l == 0) ? xgv : 0.f;
            a1 += (l == 1) ? xgv : 0.f;
            a2 += (l == 2) ? xgv : 0.f;
            a3 += (l == 3) ? xgv : 0.f;
#pragma unroll
            for (int off = 16; off > 0; off >>= 1) {
                a0 += __shfl_down_sync(0xffffffffu, a0, off);
                a1 += __shfl_down_sync(0xffffffffu, a1, off);
                a2 += __shfl_down_sync(0xffffffffu, a2, off);
                a3 += __shfl_down_sync(0xffffffffu, a3, off);
            }
            if (l == 0) {
                float ig = sigm(a0);
                float fg = sigm(a1);
                float gg = tanh_fast(a2);
                float og = sigm(a3);
                c = fg * c + ig * gg;
                float hn = og * tanh_fast(c);
                hkeep = hn;
                g_hbuf[(t + 1) & 1][j] = hn;
                g_hs[(size_t)t * H + j] = hn;
            }
        }

        __syncthreads();                         // sync #2: all writes done
        if (threadIdx.x == 0) {
            asm volatile("red.release.gpu.global.add.u32 [%0], %1;"
                         :: "l"(&g_bar), "r"(1u) : "memory");
            const unsigned target = (unsigned)(t + 1) * (unsigned)NCTA;
            unsigned v;
            do {
                asm volatile("ld.acquire.gpu.global.u32 %0, [%1];"
                             : "=r"(v) : "l"(&g_bar) : "memory");
            } while (v < target);
        }
        __syncthreads();                         // sync #3: release whole CTA
    }

    if (active && l == 0) {
        dout[OUT_BASE + j]     = hkeep;   // hT
        dout[OUT_BASE + H + j] = c;       // cT
    }
}

// ---------------- output FC: out = sigmoid(hs @ W_fc^T + b_fc) --------------
__global__ void fc_kernel(const float* __restrict__ bfc, float* __restrict__ out)
{
    const int gw = (blockIdx.x * blockDim.x + threadIdx.x) >> 5;  // 0..4095
    const int l  = threadIdx.x & 31;
    const int t0 = gw * 2;

    float ax0 = 0.f, ay0 = 0.f, ax1 = 0.f, ay1 = 0.f;
    const float* hs0 = g_hs + (size_t)t0 * H;

#pragma unroll 8
    for (int k = 0; k < H; k++) {
        float2 wv = *(const float2*)(g_WfcT + k * DOUT + 2 * l);
        float h0 = __ldg(hs0 + k);
        float h1 = __ldg(hs0 + H + k);
        ax0 = fmaf(h0, wv.x, ax0); ay0 = fmaf(h0, wv.y, ay0);
        ax1 = fmaf(h1, wv.x, ax1); ay1 = fmaf(h1, wv.y, ay1);
    }
    const float bx = bfc[2 * l], by = bfc[2 * l + 1];
    float2 o;
    o.x = sigm(ax0 + bx); o.y = sigm(ay0 + by);
    *(float2*)(out + (size_t)(t0 + 0) * DOUT + 2 * l) = o;
    o.x = sigm(ax1 + bx); o.y = sigm(ay1 + by);
    *(float2*)(out + (size_t)(t0 + 1) * DOUT + 2 * l) = o;
}

// ---------------- launch -----------------------------------------------------
extern "C" void kernel_launch(void* const* d_in, const int* in_sizes, int n_in,
                              void* d_out, int out_size)
{
    const float* x     = (const float*)d_in[0];
    const float* hprev = (const float*)d_in[1];
    const float* cprev = (const float*)d_in[2];
    const float* Wih   = (const float*)d_in[3];
    const float* Whh   = (const float*)d_in[4];
    const float* bih   = (const float*)d_in[5];
    const float* bhh   = (const float*)d_in[6];
    const float* Wfc   = (const float*)d_in[7];
    const float* bfc   = (const float*)d_in[8];
    float* out = (float*)d_out;

    const int smem_bytes = 14 * SW_ITERS * 4 * 32 * 8 + 2048 * 4;  // 180224
    cudaFuncSetAttribute(lstm_kernel,
                         cudaFuncAttributeMaxDynamicSharedMemorySize, smem_bytes);

    prep_kernel<<<4096, 256>>>(Whh, hprev, Wfc);

    dim3 gg(H4 / 64, SEQ / 64);
    xg_kernel<<<gg, 256>>>(x, Wih, bih, bhh);

    lstm_kernel<<<NCTA, NTHR, smem_bytes>>>(cprev, out);

    fc_kernel<<<512, 256>>>(bfc, out);
}